// round 9
// baseline (speedup 1.0000x reference)
#include <cuda_runtime.h>
#include <cstdint>

#define D_MODEL   512
#define ROW_BYTES 2048
#define RPB       8            // rows per batch (one per warp)
#define DEPTH     2            // ring stages
#define APC       128          // actors per CTA
#define NB        (APC / RPB)  // 16 batches per CTA

static constexpr float INT64_MAX_F = 9.2233720368547758e18f;

// ---------------------------------------------------------------------------
// mbarrier / bulk-copy primitives
// ---------------------------------------------------------------------------
__device__ __forceinline__ uint32_t s2u(const void* p) {
    uint32_t a;
    asm("{ .reg .u64 t; cvta.to.shared.u64 t, %1; cvt.u32.u64 %0, t; }"
        : "=r"(a) : "l"(p));
    return a;
}
__device__ __forceinline__ void mbar_init(uint32_t m, uint32_t cnt) {
    asm volatile("mbarrier.init.shared.b64 [%0], %1;" :: "r"(m), "r"(cnt) : "memory");
}
__device__ __forceinline__ void mbar_expect_tx(uint32_t m, uint32_t bytes) {
    asm volatile("mbarrier.arrive.expect_tx.shared.b64 _, [%0], %1;"
                 :: "r"(m), "r"(bytes) : "memory");
}
__device__ __forceinline__ void mbar_arrive(uint32_t m) {
    asm volatile("mbarrier.arrive.shared.b64 _, [%0];" :: "r"(m) : "memory");
}
__device__ __forceinline__ void mbar_wait(uint32_t m, uint32_t parity) {
    asm volatile(
        "{\n\t.reg .pred P;\n"
        "W_%=:\n\t"
        "mbarrier.try_wait.parity.acquire.cta.shared::cta.b64 P, [%0], %1, 0x989680;\n\t"
        "@P bra D_%=;\n\t"
        "bra W_%=;\n"
        "D_%=:\n\t}"
        :: "r"(m), "r"(parity) : "memory");
}
__device__ __forceinline__ void bulk_g2s(uint32_t dst, const void* src,
                                         uint32_t bytes, uint32_t mbar) {
    asm volatile(
        "cp.async.bulk.shared::cluster.global.mbarrier::complete_tx::bytes "
        "[%0], [%1], %2, [%3];"
        :: "r"(dst), "l"(src), "r"(bytes), "r"(mbar) : "memory");
}

// ---------------------------------------------------------------------------
// Fused lgamma + digamma for t in [1, ~9] (shift-by-4 asymptotic).
// ---------------------------------------------------------------------------
__device__ __forceinline__ void lgamma_digamma(float t, float& lg, float& dg) {
    const float u = t * (t + 3.0f);
    const float d = u * (u + 2.0f);
    const float y = t + 4.0f;
    const float ln_y  = logf(y);
    const float inv_y = __fdividef(1.0f, y);
    const float inv2  = inv_y * inv_y;
    const float inv_d = __fdividef(1.0f, d);
    const float r    = (2.0f * t + 3.0f) * (2.0f * u + 2.0f) * inv_d;
    const float ln_p = logf(d);

    lg = fmaf(y - 0.5f, ln_y, -y) + 0.918938533204672742f
       + inv_y * (0.0833333333333f - inv2 * (0.00277777777778f - inv2 * 0.000793650793651f))
       - ln_p;
    dg = ln_y - 0.5f * inv_y
       - inv2 * (0.0833333333333f - inv2 * (0.00833333333333f - inv2 * 0.00396825396825f))
       - r;
}

// ---------------------------------------------------------------------------
// Bulk-async pipelined kernel. Each CTA owns APC actors.
//   producer (thread 0): cp.async.bulk 8 rows/batch into a 2-stage smem ring
//   consumers (8 warps): one row per warp from smem, dot + butterfly, stash a,bb
//   tail: CTA-parallel epilogue, coalesced stores
// In-flight bulk bytes cost no registers -> deep pipeline at low reg pressure.
// ---------------------------------------------------------------------------
__global__ void __launch_bounds__(256)
cah_kernel(const float* __restrict__ x,
           const int*   __restrict__ actors,
           const float* __restrict__ w,
           const float* __restrict__ bvec,
           const int*   __restrict__ prev,
           float*       __restrict__ out,
           int n_actors)
{
    __shared__ __align__(128) float    stage[DEPTH][RPB * D_MODEL]; // 2 x 16KB
    __shared__ float2   sh_ab[APC];
    __shared__ int      sh_idx[APC];
    __shared__ __align__(8) uint64_t mbar_storage[2 * DEPTH];       // full[0..1], empty[2..3]

    const int tid  = threadIdx.x;
    const int lane = tid & 31;
    const int wid  = tid >> 5;
    const int base = blockIdx.x * APC;

    const uint32_t mb = s2u(mbar_storage);
    const uint32_t full_bar[DEPTH]  = { mb,      mb + 8  };
    const uint32_t empty_bar[DEPTH] = { mb + 16, mb + 24 };

    // Preload w into registers (lane covers columns j*128 + lane*4)
    float4 w0r[4], w1r[4];
    #pragma unroll
    for (int j = 0; j < 4; j++) {
        int c = j * 128 + lane * 4;
        w0r[j] = *reinterpret_cast<const float4*>(w + c);
        w1r[j] = *reinterpret_cast<const float4*>(w + D_MODEL + c);
    }
    const float b0 = bvec[0];
    const float b1 = bvec[1];

    // Stage actor indices (clamped for generality)
    if (tid < APC) {
        int g = base + tid;
        sh_idx[tid] = actors[g < n_actors ? g : (n_actors - 1)];
    }
    if (tid == 0) {
        #pragma unroll
        for (int d = 0; d < DEPTH; d++) {
            mbar_init(full_bar[d], 1);     // completed by expect_tx drain
            mbar_init(empty_bar[d], RPB);  // one arrive per consumer warp
        }
    }
    __syncthreads();

    // Prologue: fill both stages
    if (tid == 0) {
        #pragma unroll
        for (int d = 0; d < DEPTH; d++) {
            mbar_expect_tx(full_bar[d], RPB * ROW_BYTES);
            const uint32_t dst0 = s2u(stage[d]);
            #pragma unroll
            for (int r = 0; r < RPB; r++) {
                const float* src = x + (size_t)sh_idx[d * RPB + r] * D_MODEL;
                bulk_g2s(dst0 + r * ROW_BYTES, src, ROW_BYTES, full_bar[d]);
            }
        }
    }

    // Main loop over batches
    for (int s = 0; s < NB; s++) {
        const int slot      = s & 1;
        const uint32_t ph   = (uint32_t)((s >> 1) & 1);

        mbar_wait(full_bar[slot], ph);

        // Warp `wid` consumes row `wid` of this stage
        const float* row = &stage[slot][wid * D_MODEL];
        float s0 = 0.0f, s1 = 0.0f;
        #pragma unroll
        for (int j = 0; j < 4; j++) {
            const float4 v = *reinterpret_cast<const float4*>(row + (j * 32 + lane) * 4);
            s0 = fmaf(v.x, w0r[j].x, s0); s0 = fmaf(v.y, w0r[j].y, s0);
            s0 = fmaf(v.z, w0r[j].z, s0); s0 = fmaf(v.w, w0r[j].w, s0);
            s1 = fmaf(v.x, w1r[j].x, s1); s1 = fmaf(v.y, w1r[j].y, s1);
            s1 = fmaf(v.z, w1r[j].z, s1); s1 = fmaf(v.w, w1r[j].w, s1);
        }
        #pragma unroll
        for (int off = 16; off > 0; off >>= 1) {
            s0 += __shfl_xor_sync(0xffffffffu, s0, off);
            s1 += __shfl_xor_sync(0xffffffffu, s1, off);
        }
        if (lane == 0) {
            const float z0 = s0 + b0;
            const float z1 = s1 + b1;
            float2 ab;
            ab.x = fmaf(z0, z0, 1.0f);
            ab.y = fmaf(z1, z1, 1.0f);
            sh_ab[s * RPB + wid] = ab;
            mbar_arrive(empty_bar[slot]);
        }

        // Producer: refill this slot with batch s+DEPTH once all warps emptied it
        if (tid == 0 && s + DEPTH < NB) {
            mbar_wait(empty_bar[slot], ph);
            mbar_expect_tx(full_bar[slot], RPB * ROW_BYTES);
            const uint32_t dst0 = s2u(stage[slot]);
            const int tb = (s + DEPTH) * RPB;
            #pragma unroll
            for (int r = 0; r < RPB; r++) {
                const float* src = x + (size_t)sh_idx[tb + r] * D_MODEL;
                bulk_g2s(dst0 + r * ROW_BYTES, src, ROW_BYTES, full_bar[slot]);
            }
        }
    }

    __syncthreads();

    // CTA-parallel epilogue: one actor per thread (tid < APC)
    if (tid < APC) {
        const int i = base + tid;
        if (i < n_actors) {
            const float2 ab = sh_ab[tid];
            const float a  = ab.x;
            const float bb = ab.y;

            const float pa     = (float)__ldg(prev + i);
            const float action = pa * (1.0f / INT64_MAX_F);

            float lga, dga, lgb, dgb, lgab, dgab;
            lgamma_digamma(a,      lga,  dga);
            lgamma_digamma(bb,     lgb,  dgb);
            lgamma_digamma(a + bb, lgab, dgab);

            const float lbeta = lga + lgb - lgab;

            const float logprob = (a - 1.0f) * logf(action)
                                + (bb - 1.0f) * log1pf(-action)
                                - lbeta;

            const float ent = lbeta
                            - (a - 1.0f)  * dga
                            - (bb - 1.0f) * dgb
                            + (a + bb - 2.0f) * dgab;

            out[i]                        = action * INT64_MAX_F;
            out[(size_t)n_actors + i]     = logprob;
            out[2 * (size_t)n_actors + i] = ent;
            float2 l; l.x = a; l.y = bb;
            *reinterpret_cast<float2*>(out + 3 * (size_t)n_actors + 2 * (size_t)i) = l;
        }
    }
}

extern "C" void kernel_launch(void* const* d_in, const int* in_sizes, int n_in,
                              void* d_out, int out_size)
{
    const float* x      = (const float*)d_in[0];
    const int*   actors = (const int*)  d_in[1];
    const float* w      = (const float*)d_in[2];
    const float* bvec   = (const float*)d_in[3];
    const int*   prev   = (const int*)  d_in[4];
    float*       out    = (float*)d_out;

    const int n_actors = in_sizes[1];  // 262144

    const int blocks = (n_actors + APC - 1) / APC;  // 2048
    cah_kernel<<<blocks, 256>>>(x, actors, w, bvec, prev, out, n_actors);
}

// round 10
// speedup vs baseline: 1.4773x; 1.4773x over previous
#include <cuda_runtime.h>

#define D_MODEL 512
static constexpr float INT64_MAX_F = 9.2233720368547758e18f;

// ---------------------------------------------------------------------------
// Fused lgamma + digamma for t in [1, ~9]. Shift by 4 (y = t+4 >= 5),
// asymptotic series; recurrence product t(t+1)(t+2)(t+3) = u(u+2), u=t^2+3t.
// ---------------------------------------------------------------------------
__device__ __forceinline__ void lgamma_digamma(float t, float& lg, float& dg) {
    const float u = t * (t + 3.0f);
    const float d = u * (u + 2.0f);
    const float y = t + 4.0f;
    const float ln_y  = logf(y);
    const float inv_y = __fdividef(1.0f, y);
    const float inv2  = inv_y * inv_y;
    const float inv_d = __fdividef(1.0f, d);
    const float r    = (2.0f * t + 3.0f) * (2.0f * u + 2.0f) * inv_d;
    const float ln_p = logf(d);

    lg = fmaf(y - 0.5f, ln_y, -y) + 0.918938533204672742f
       + inv_y * (0.0833333333333f - inv2 * (0.00277777777778f - inv2 * 0.000793650793651f))
       - ln_p;
    dg = ln_y - 0.5f * inv_y
       - inv2 * (0.0833333333333f - inv2 * (0.00833333333333f - inv2 * 0.00396825396825f))
       - r;
}

// ---------------------------------------------------------------------------
// Kernel A: gather + dual dot. One warp handles 4 actors; w lives in SHARED
// MEMORY (4KB) instead of 32 registers -> regs drop, occupancy cap rises,
// more warps resident to hide the ~600cyc gather latency.
// shw access shw[j*32+lane] is LDS.128 conflict-free (each 8-lane phase
// covers all 32 banks exactly once).
// ---------------------------------------------------------------------------
__global__ void __launch_bounds__(256)
cah_gemv_kernel(const float* __restrict__ x,
                const int*   __restrict__ actors,
                const float* __restrict__ w,
                const float* __restrict__ bvec,
                float*       __restrict__ out,
                int n_actors)
{
    __shared__ float4 shw[256];   // [0..127] = w row 0, [128..255] = w row 1

    const int tid  = threadIdx.x;
    const int lane = tid & 31;
    const int warp = (blockIdx.x * blockDim.x + tid) >> 5;

    // stage w: 1024 floats = 256 float4, one per thread
    shw[tid] = reinterpret_cast<const float4*>(w)[tid];
    __syncthreads();

    const int i0 = warp * 4;
    if (i0 >= n_actors) return;

    const float b0 = bvec[0];
    const float b1 = bvec[1];

    // Row pointers for the 4 actors
    const float4* xr[4];
    #pragma unroll
    for (int q = 0; q < 4; q++) {
        const int idx = (i0 + q < n_actors) ? (i0 + q) : i0;
        const int row = __ldg(actors + idx);
        xr[q] = reinterpret_cast<const float4*>(x + (size_t)row * D_MODEL);
    }

    // 16 independent 16B gathers per lane, all issued before any use
    float4 v[4][4];
    #pragma unroll
    for (int q = 0; q < 4; q++)
        #pragma unroll
        for (int j = 0; j < 4; j++)
            v[q][j] = __ldg(xr[q] + j * 32 + lane);

    float acc[4][2];
    #pragma unroll
    for (int q = 0; q < 4; q++) { acc[q][0] = 0.0f; acc[q][1] = 0.0f; }

    #pragma unroll
    for (int j = 0; j < 4; j++) {
        const float4 w0 = shw[j * 32 + lane];
        const float4 w1 = shw[128 + j * 32 + lane];
        #pragma unroll
        for (int q = 0; q < 4; q++) {
            float s0 = acc[q][0], s1 = acc[q][1];
            s0 = fmaf(v[q][j].x, w0.x, s0); s0 = fmaf(v[q][j].y, w0.y, s0);
            s0 = fmaf(v[q][j].z, w0.z, s0); s0 = fmaf(v[q][j].w, w0.w, s0);
            s1 = fmaf(v[q][j].x, w1.x, s1); s1 = fmaf(v[q][j].y, w1.y, s1);
            s1 = fmaf(v[q][j].z, w1.z, s1); s1 = fmaf(v[q][j].w, w1.w, s1);
            acc[q][0] = s0; acc[q][1] = s1;
        }
    }

    // Butterfly-reduce all 8 partial sums
    #pragma unroll
    for (int off = 16; off > 0; off >>= 1) {
        #pragma unroll
        for (int q = 0; q < 4; q++) {
            acc[q][0] += __shfl_xor_sync(0xffffffffu, acc[q][0], off);
            acc[q][1] += __shfl_xor_sync(0xffffffffu, acc[q][1], off);
        }
    }

    if (lane == 0) {
        float lg[8];
        #pragma unroll
        for (int q = 0; q < 4; q++) {
            const float z0 = acc[q][0] + b0;
            const float z1 = acc[q][1] + b1;
            lg[2*q]   = fmaf(z0, z0, 1.0f);
            lg[2*q+1] = fmaf(z1, z1, 1.0f);
        }
        float* lbase = out + 3 * (size_t)n_actors + 2 * (size_t)i0;
        if (i0 + 3 < n_actors) {
            *reinterpret_cast<float4*>(lbase)     = make_float4(lg[0], lg[1], lg[2], lg[3]);
            *reinterpret_cast<float4*>(lbase + 4) = make_float4(lg[4], lg[5], lg[6], lg[7]);
        } else {
            for (int q = 0; q < 4 && i0 + q < n_actors; q++) {
                lbase[2*q]   = lg[2*q];
                lbase[2*q+1] = lg[2*q+1];
            }
        }
    }
}

// ---------------------------------------------------------------------------
// Kernel B: fully parallel epilogue. One thread per actor.
// ---------------------------------------------------------------------------
__global__ void __launch_bounds__(256)
cah_epilogue_kernel(const int* __restrict__ prev,
                    float*     __restrict__ out,
                    int n_actors)
{
    const int i = blockIdx.x * blockDim.x + threadIdx.x;
    if (i >= n_actors) return;

    const float2 l = *reinterpret_cast<const float2*>(out + 3 * (size_t)n_actors + 2 * (size_t)i);
    const float a  = l.x;
    const float bb = l.y;

    const float pa     = (float)__ldg(prev + i);
    const float action = pa * (1.0f / INT64_MAX_F);

    float lga, dga, lgb, dgb, lgab, dgab;
    lgamma_digamma(a,      lga,  dga);
    lgamma_digamma(bb,     lgb,  dgb);
    lgamma_digamma(a + bb, lgab, dgab);

    const float lbeta = lga + lgb - lgab;

    const float logprob = (a - 1.0f) * logf(action)
                        + (bb - 1.0f) * log1pf(-action)
                        - lbeta;

    const float ent = lbeta
                    - (a - 1.0f)  * dga
                    - (bb - 1.0f) * dgb
                    + (a + bb - 2.0f) * dgab;

    out[i]                        = action * INT64_MAX_F;
    out[(size_t)n_actors + i]     = logprob;
    out[2 * (size_t)n_actors + i] = ent;
}

extern "C" void kernel_launch(void* const* d_in, const int* in_sizes, int n_in,
                              void* d_out, int out_size)
{
    const float* x      = (const float*)d_in[0];
    const int*   actors = (const int*)  d_in[1];
    const float* w      = (const float*)d_in[2];
    const float* bvec   = (const float*)d_in[3];
    const int*   prev   = (const int*)  d_in[4];
    float*       out    = (float*)d_out;

    const int n_actors = in_sizes[1];  // 262144

    const int T = 256;

    // Kernel A: 4 actors per warp
    const int warpsA  = (n_actors + 3) / 4;
    const int blocksA = (warpsA * 32 + T - 1) / T;
    cah_gemv_kernel<<<blocksA, T>>>(x, actors, w, bvec, out, n_actors);

    // Kernel B: 1 thread per actor
    const int blocksB = (n_actors + T - 1) / T;
    cah_epilogue_kernel<<<blocksB, T>>>(prev, out, n_actors);
}

// round 11
// speedup vs baseline: 1.5045x; 1.0184x over previous
#include <cuda_runtime.h>

#define D_MODEL 512
static constexpr float INT64_MAX_F = 9.2233720368547758e18f;

// ---------------------------------------------------------------------------
// Fused lgamma + digamma for t in [1, ~9] (shift-by-4 asymptotic).
// ---------------------------------------------------------------------------
__device__ __forceinline__ void lgamma_digamma(float t, float& lg, float& dg) {
    const float u = t * (t + 3.0f);
    const float d = u * (u + 2.0f);
    const float y = t + 4.0f;
    const float ln_y  = logf(y);
    const float inv_y = __fdividef(1.0f, y);
    const float inv2  = inv_y * inv_y;
    const float inv_d = __fdividef(1.0f, d);
    const float r    = (2.0f * t + 3.0f) * (2.0f * u + 2.0f) * inv_d;
    const float ln_p = logf(d);

    lg = fmaf(y - 0.5f, ln_y, -y) + 0.918938533204672742f
       + inv_y * (0.0833333333333f - inv2 * (0.00277777777778f - inv2 * 0.000793650793651f))
       - ln_p;
    dg = ln_y - 0.5f * inv_y
       - inv2 * (0.0833333333333f - inv2 * (0.00833333333333f - inv2 * 0.00396825396825f))
       - r;
}

// ---------------------------------------------------------------------------
// Kernel A: software-pipelined gather+dot. Each warp grid-strides over actor
// PAIRS with a double-buffered register file: loads for pair k+1 are issued
// BEFORE consuming pair k, so the warp always has 8 float4 gathers in flight,
// including during the FMA/shuffle/store phase.
// ---------------------------------------------------------------------------
struct PairBuf { float4 v[2][4]; };   // [actor-in-pair][chunk]

__device__ __forceinline__ void issue_pair(const float* __restrict__ x,
                                           const int*   __restrict__ actors,
                                           int pair, int lane, PairBuf& b)
{
    const int  ia = 2 * pair;
    const float4* xa = reinterpret_cast<const float4*>(x + (size_t)__ldg(actors + ia)     * D_MODEL);
    const float4* xb = reinterpret_cast<const float4*>(x + (size_t)__ldg(actors + ia + 1) * D_MODEL);
    #pragma unroll
    for (int j = 0; j < 4; j++) b.v[0][j] = __ldg(xa + j * 32 + lane);
    #pragma unroll
    for (int j = 0; j < 4; j++) b.v[1][j] = __ldg(xb + j * 32 + lane);
}

__device__ __forceinline__ void consume_pair(const PairBuf& bf,
                                             const float4 (&w0r)[4], const float4 (&w1r)[4],
                                             float b0, float b1,
                                             int pair, int lane,
                                             float* __restrict__ lbase)
{
    float a0 = 0.0f, a1 = 0.0f, c0 = 0.0f, c1 = 0.0f;
    #pragma unroll
    for (int j = 0; j < 4; j++) {
        const float4 va = bf.v[0][j];
        const float4 vb = bf.v[1][j];
        a0 = fmaf(va.x, w0r[j].x, a0); a0 = fmaf(va.y, w0r[j].y, a0);
        a0 = fmaf(va.z, w0r[j].z, a0); a0 = fmaf(va.w, w0r[j].w, a0);
        a1 = fmaf(va.x, w1r[j].x, a1); a1 = fmaf(va.y, w1r[j].y, a1);
        a1 = fmaf(va.z, w1r[j].z, a1); a1 = fmaf(va.w, w1r[j].w, a1);
        c0 = fmaf(vb.x, w0r[j].x, c0); c0 = fmaf(vb.y, w0r[j].y, c0);
        c0 = fmaf(vb.z, w0r[j].z, c0); c0 = fmaf(vb.w, w0r[j].w, c0);
        c1 = fmaf(vb.x, w1r[j].x, c1); c1 = fmaf(vb.y, w1r[j].y, c1);
        c1 = fmaf(vb.z, w1r[j].z, c1); c1 = fmaf(vb.w, w1r[j].w, c1);
    }
    #pragma unroll
    for (int off = 16; off > 0; off >>= 1) {
        a0 += __shfl_xor_sync(0xffffffffu, a0, off);
        a1 += __shfl_xor_sync(0xffffffffu, a1, off);
        c0 += __shfl_xor_sync(0xffffffffu, c0, off);
        c1 += __shfl_xor_sync(0xffffffffu, c1, off);
    }
    if (lane == 0) {
        const float za0 = a0 + b0, za1 = a1 + b1;
        const float zb0 = c0 + b0, zb1 = c1 + b1;
        float4 o;
        o.x = fmaf(za0, za0, 1.0f);
        o.y = fmaf(za1, za1, 1.0f);
        o.z = fmaf(zb0, zb0, 1.0f);
        o.w = fmaf(zb1, zb1, 1.0f);
        *reinterpret_cast<float4*>(lbase + 4 * (size_t)pair) = o;
    }
}

__global__ void __launch_bounds__(256)
cah_gemv_kernel(const float* __restrict__ x,
                const int*   __restrict__ actors,
                const float* __restrict__ w,
                const float* __restrict__ bvec,
                float*       __restrict__ out,
                int n_actors)
{
    const int tid   = threadIdx.x;
    const int lane  = tid & 31;
    const int gwarp = (blockIdx.x * blockDim.x + tid) >> 5;
    const int nwarp = (gridDim.x * blockDim.x) >> 5;
    const int npairs = n_actors >> 1;   // n_actors even

    float4 w0r[4], w1r[4];
    #pragma unroll
    for (int j = 0; j < 4; j++) {
        int c = j * 128 + lane * 4;
        w0r[j] = *reinterpret_cast<const float4*>(w + c);
        w1r[j] = *reinterpret_cast<const float4*>(w + D_MODEL + c);
    }
    const float b0 = bvec[0];
    const float b1 = bvec[1];
    float* lbase = out + 3 * (size_t)n_actors;

    int p0 = gwarp;
    if (p0 >= npairs) return;

    PairBuf A, B;
    issue_pair(x, actors, p0, lane, A);

    for (;;) {
        const int p1 = p0 + nwarp;
        if (p1 < npairs) issue_pair(x, actors, p1, lane, B);
        consume_pair(A, w0r, w1r, b0, b1, p0, lane, lbase);
        if (p1 >= npairs) return;

        const int p2 = p1 + nwarp;
        if (p2 < npairs) issue_pair(x, actors, p2, lane, A);
        consume_pair(B, w0r, w1r, b0, b1, p1, lane, lbase);
        if (p2 >= npairs) return;

        p0 = p2;
    }
}

// ---------------------------------------------------------------------------
// Kernel B: fully parallel epilogue. One thread per actor.
// ---------------------------------------------------------------------------
__global__ void __launch_bounds__(256)
cah_epilogue_kernel(const int* __restrict__ prev,
                    float*     __restrict__ out,
                    int n_actors)
{
    const int i = blockIdx.x * blockDim.x + threadIdx.x;
    if (i >= n_actors) return;

    const float2 l = *reinterpret_cast<const float2*>(out + 3 * (size_t)n_actors + 2 * (size_t)i);
    const float a  = l.x;
    const float bb = l.y;

    const float pa     = (float)__ldg(prev + i);
    const float action = pa * (1.0f / INT64_MAX_F);

    float lga, dga, lgb, dgb, lgab, dgab;
    lgamma_digamma(a,      lga,  dga);
    lgamma_digamma(bb,     lgb,  dgb);
    lgamma_digamma(a + bb, lgab, dgab);

    const float lbeta = lga + lgb - lgab;

    const float logprob = (a - 1.0f) * logf(action)
                        + (bb - 1.0f) * log1pf(-action)
                        - lbeta;

    const float ent = lbeta
                    - (a - 1.0f)  * dga
                    - (bb - 1.0f) * dgb
                    + (a + bb - 2.0f) * dgab;

    out[i]                        = action * INT64_MAX_F;
    out[(size_t)n_actors + i]     = logprob;
    out[2 * (size_t)n_actors + i] = ent;
}

extern "C" void kernel_launch(void* const* d_in, const int* in_sizes, int n_in,
                              void* d_out, int out_size)
{
    const float* x      = (const float*)d_in[0];
    const int*   actors = (const int*)  d_in[1];
    const float* w      = (const float*)d_in[2];
    const float* bvec   = (const float*)d_in[3];
    const int*   prev   = (const int*)  d_in[4];
    float*       out    = (float*)d_out;

    const int n_actors = in_sizes[1];  // 262144

    const int T = 256;

    // Kernel A: 2048 CTAs = 16384 warps -> 8 pairs per warp, double-buffered.
    const int blocksA = 2048;
    cah_gemv_kernel<<<blocksA, T>>>(x, actors, w, bvec, out, n_actors);

    // Kernel B: 1 thread per actor
    const int blocksB = (n_actors + T - 1) / T;
    cah_epilogue_kernel<<<blocksB, T>>>(prev, out, n_actors);
}